// round 1
// baseline (speedup 1.0000x reference)
#include <cuda_runtime.h>
#include <math.h>

#define Vv      40
#define Ee      512
#define Hh      512
#define DKk     512
#define DVv     512
#define TENC    8192
#define MAXLEN  200
#define EOSI    38
#define SCALE   0.04419417382415922f   /* 1/sqrt(512) */

#define TPB     512
#define WPB     (TPB/32)
#define MAXB    256

// -------- persistent device scratch (no allocations allowed) --------
__device__ float    g_GI[3*Hh*Vv];      // w_ih @ embed^T + b_ih   [1536][40]
__device__ float    g_WV[TENC*Vv];      // values @ w_out[:, :512]^T  [8192][40]
__device__ float    g_hbuf[2][Hh];      // hidden ping-pong
__device__ float    g_pOutU[MAXB*Vv];   // per-block partial  sum_t e_t*WV[t][k]
__device__ float    g_pDen[MAXB];       // per-block partial  sum_t e_t
__device__ float    g_pOutH[Vv];        // w_out[:,512:] @ h
__device__ float    g_denom[MAXLEN];    // softmax denominators per step
__device__ unsigned g_cnt;
__device__ unsigned g_gen;

// -------- lightweight grid barrier (all blocks co-resident: grid <= #SM) ----
__device__ __forceinline__ void gridbar()
{
    __syncthreads();
    if (threadIdx.x == 0) {
        __threadfence();                       // release my stores to L2
        unsigned gen = *(volatile unsigned*)&g_gen;
        unsigned nb  = gridDim.x;
        if (atomicAdd(&g_cnt, 1u) == nb - 1u) {
            g_cnt = 0;
            __threadfence();
            *(volatile unsigned*)&g_gen = gen + 1u;
        } else {
            while (*(volatile unsigned*)&g_gen == gen) { }
        }
        __threadfence();                       // acquire: invalidate stale L1
    }
    __syncthreads();
}

__global__ void init_kernel()
{
    if (threadIdx.x == 0) { g_cnt = 0; g_gen = 0; }
}

// -------- GI = w_ih @ embed^T + b_ih : one warp per row of w_ih -------------
__global__ void gi_kernel(const float* __restrict__ w_ih,
                          const float* __restrict__ b_ih,
                          const float* __restrict__ embed)
{
    extern __shared__ float sE[];              // embed [40][512] = 80 KB
    for (int i = threadIdx.x; i < Vv*Ee; i += blockDim.x) sE[i] = embed[i];
    __syncthreads();

    int lane = threadIdx.x & 31;
    int gid  = blockIdx.x * (blockDim.x >> 5) + (threadIdx.x >> 5);
    if (gid >= 3*Hh) return;

    float wreg[16];
    const float* wr = w_ih + (size_t)gid * Ee;
    #pragma unroll
    for (int j = 0; j < 16; ++j) wreg[j] = wr[lane + 32*j];
    float bb = b_ih[gid];

    for (int v = 0; v < Vv; ++v) {
        float a = 0.f;
        #pragma unroll
        for (int j = 0; j < 16; ++j) a = fmaf(wreg[j], sE[v*Ee + lane + 32*j], a);
        #pragma unroll
        for (int o = 16; o > 0; o >>= 1) a += __shfl_down_sync(0xffffffffu, a, o);
        if (lane == 0) g_GI[(size_t)gid*Vv + v] = a + bb;
    }
}

// -------- WV[t][k] = dot(values[t], w_out[k][0:512]) : one warp per t -------
__global__ void wv_kernel(const float* __restrict__ enc,
                          const float* __restrict__ w_out)
{
    extern __shared__ float sW[];              // w_out[:, :512] [40][512] = 80 KB
    for (int i = threadIdx.x; i < Vv*DVv; i += blockDim.x) {
        int k = i / DVv, j = i % DVv;
        sW[i] = w_out[(size_t)k*(DVv+Hh) + j];
    }
    __syncthreads();

    int lane  = threadIdx.x & 31;
    int gw    = blockIdx.x * (blockDim.x >> 5) + (threadIdx.x >> 5);
    int wspan = gridDim.x  * (blockDim.x >> 5);

    for (int t = gw; t < TENC; t += wspan) {
        float vreg[16];
        const float* vr = enc + (size_t)t*(DKk+DVv) + DKk;
        #pragma unroll
        for (int j = 0; j < 16; ++j) vreg[j] = vr[lane + 32*j];
        for (int k = 0; k < Vv; ++k) {
            float a = 0.f;
            #pragma unroll
            for (int j = 0; j < 16; ++j) a = fmaf(vreg[j], sW[k*DVv + lane + 32*j], a);
            #pragma unroll
            for (int o = 16; o > 0; o >>= 1) a += __shfl_down_sync(0xffffffffu, a, o);
            if (lane == 0) g_WV[(size_t)t*Vv + k] = a;
        }
    }
}

// -------- persistent decoder kernel ----------------------------------------
__global__ void __launch_bounds__(TPB)
dec_main(const float* __restrict__ enc,
         const float* __restrict__ hidden,
         const float* __restrict__ w_hh,
         const float* __restrict__ b_hh,
         const float* __restrict__ w_out,
         const float* __restrict__ b_out,
         float*       __restrict__ dout)
{
    __shared__ float h_sh[Hh];
    __shared__ float s_out[Vv];
    __shared__ float sOutU[WPB][Vv];
    __shared__ float sDen[WPB];
    __shared__ int   s_best;
    __shared__ float s_invden;

    const int tid  = threadIdx.x;
    const int wid  = tid >> 5;
    const int lane = tid & 31;
    const int b    = blockIdx.x;
    const int nb   = gridDim.x;

    float* attn = dout + (MAXLEN*Vv + 1);      // attention region of d_out

    const int  gid        = b*WPB + wid;       // global warp id
    const bool needs_best = (b*WPB) < Hh;      // blocks owning GRU rows
    int  mylen = MAXLEN;                       // block 0 / thread 0 only
    int  best  = EOSI;                         // initial input = embed[EOS]

    const int tile = (TENC + nb - 1) / nb;
    const int t0   = b * tile;

    for (int s = 0; s < MAXLEN; ++s) {
        // ---------- phase 1: inline argmax of previous step + GRU ----------
        if (needs_best) {
            const float* hsrc = (s == 0) ? hidden : g_hbuf[(s-1)&1];
            for (int i = tid; i < Hh; i += TPB) h_sh[i] = hsrc[i];
        }

        if (s > 0 && needs_best) {
            // deterministic fixed-order reduction of per-block partials
            if (tid < Vv) {
                float a = 0.f;
                for (int p = 0; p < nb; ++p) a += g_pOutU[p*Vv + tid];
                s_out[tid] = a;
            } else if (tid == Vv) {
                float d = 0.f;
                for (int p = 0; p < nb; ++p) d += g_pDen[p];
                s_invden = 1.0f / d;
                if (b == 0) g_denom[s-1] = d;
            }
            __syncthreads();
            if (tid == 0) {
                float bv = -3.4e38f; int bi = 0;
                float inv = s_invden;
                for (int k = 0; k < Vv; ++k) {
                    float o = s_out[k]*inv + g_pOutH[k] + b_out[k];
                    s_out[k] = o;
                    if (o > bv) { bv = o; bi = k; }
                }
                s_best = bi;
            }
            __syncthreads();
            best = s_best;
            if (b == 0) {
                if (tid < Vv) dout[(s-1)*Vv + tid] = s_out[tid];
                if (tid == 0 && best == EOSI && mylen == MAXLEN) mylen = s-1;
            }
        }
        __syncthreads();

        // GRU: one warp per hidden index i (3 dots of 512 over w_hh)
        if (gid < Hh) {
            const int i = gid;
            const float* r0 = w_hh + (size_t)i*Hh;
            const float* r1 = w_hh + (size_t)(Hh   + i)*Hh;
            const float* r2 = w_hh + (size_t)(2*Hh + i)*Hh;
            float a0 = 0.f, a1 = 0.f, a2 = 0.f;
            #pragma unroll
            for (int j = 0; j < Hh/32; ++j) {
                float hv = h_sh[lane + 32*j];
                a0 = fmaf(r0[lane + 32*j], hv, a0);
                a1 = fmaf(r1[lane + 32*j], hv, a1);
                a2 = fmaf(r2[lane + 32*j], hv, a2);
            }
            #pragma unroll
            for (int o = 16; o > 0; o >>= 1) {
                a0 += __shfl_down_sync(0xffffffffu, a0, o);
                a1 += __shfl_down_sync(0xffffffffu, a1, o);
                a2 += __shfl_down_sync(0xffffffffu, a2, o);
            }
            if (lane == 0) {
                float ghr = a0 + b_hh[i];
                float ghz = a1 + b_hh[Hh + i];
                float ghn = a2 + b_hh[2*Hh + i];
                float gir = g_GI[(size_t)i*Vv          + best];
                float giz = g_GI[(size_t)(Hh   + i)*Vv + best];
                float gin = g_GI[(size_t)(2*Hh + i)*Vv + best];
                float rr = 1.f/(1.f + expf(-(gir + ghr)));
                float zz = 1.f/(1.f + expf(-(giz + ghz)));
                float nn = tanhf(gin + rr*ghn);
                g_hbuf[s&1][i] = (1.f - zz)*nn + zz*h_sh[i];
            }
        }
        gridbar();

        // ---------- phase 2: attention scores + fused output accumulation ----
        {
            const float* hq = g_hbuf[s&1];
            for (int i = tid; i < Hh; i += TPB) h_sh[i] = hq[i];
            __syncthreads();

            // block 0: out_h = w_out[:, 512:] @ h
            if (b == 0) {
                for (int k = wid; k < Vv; k += WPB) {
                    const float* wr = w_out + (size_t)k*(DVv+Hh) + DVv;
                    float a = 0.f;
                    #pragma unroll
                    for (int j = 0; j < Hh/32; ++j)
                        a = fmaf(wr[lane + 32*j], h_sh[lane + 32*j], a);
                    #pragma unroll
                    for (int o = 16; o > 0; o >>= 1) a += __shfl_down_sync(0xffffffffu, a, o);
                    if (lane == 0) g_pOutH[k] = a;
                }
            }

            float acc0 = 0.f, acc1 = 0.f, den = 0.f;
            for (int jt = wid; jt < tile; jt += WPB) {
                int t = t0 + jt;
                if (t < TENC) {
                    const float* kr = enc + (size_t)t*(DKk+DVv);
                    float a = 0.f;
                    #pragma unroll
                    for (int j = 0; j < DKk/32; ++j)
                        a = fmaf(kr[lane + 32*j], h_sh[lane + 32*j], a);
                    #pragma unroll
                    for (int o = 16; o > 0; o >>= 1) a += __shfl_down_sync(0xffffffffu, a, o);
                    a = __shfl_sync(0xffffffffu, a, 0);
                    float e = expf(a * SCALE);
                    if (lane == 0) attn[(size_t)s*TENC + t] = e;   // unnormalized
                    den += e;
                    acc0 = fmaf(e, g_WV[(size_t)t*Vv + lane], acc0);
                    if (lane < Vv - 32)
                        acc1 = fmaf(e, g_WV[(size_t)t*Vv + 32 + lane], acc1);
                }
            }
            sOutU[wid][lane] = acc0;
            if (lane < Vv - 32) sOutU[wid][32 + lane] = acc1;
            if (lane == 0)      sDen[wid] = den;
            __syncthreads();
            if (tid < Vv) {
                float a = 0.f;
                #pragma unroll
                for (int w = 0; w < WPB; ++w) a += sOutU[w][tid];
                g_pOutU[(size_t)b*Vv + tid] = a;
            } else if (tid == Vv) {
                float d = 0.f;
                #pragma unroll
                for (int w = 0; w < WPB; ++w) d += sDen[w];
                g_pDen[b] = d;
            }
        }
        gridbar();
    }

    // ---------- tail: final step's logits/argmax + EOS length ----------
    if (b == 0) {
        if (tid < Vv) {
            float a = 0.f;
            for (int p = 0; p < nb; ++p) a += g_pOutU[p*Vv + tid];
            s_out[tid] = a;
        } else if (tid == Vv) {
            float d = 0.f;
            for (int p = 0; p < nb; ++p) d += g_pDen[p];
            s_invden = 1.0f / d;
            g_denom[MAXLEN-1] = d;
        }
        __syncthreads();
        if (tid == 0) {
            float bv = -3.4e38f; int bi = 0;
            for (int k = 0; k < Vv; ++k) {
                float o = s_out[k]*s_invden + g_pOutH[k] + b_out[k];
                s_out[k] = o;
                if (o > bv) { bv = o; bi = k; }
            }
            if (bi == EOSI && mylen == MAXLEN) mylen = MAXLEN-1;
            dout[MAXLEN*Vv] = (float)mylen;            // lens
        }
        __syncthreads();
        if (tid < Vv) dout[(MAXLEN-1)*Vv + tid] = s_out[tid];
    }
    gridbar();

    // ---------- bulk normalization of attentions ----------
    {
        const long long total = (long long)MAXLEN * TENC;
        for (long long idx = (long long)b*TPB + tid; idx < total;
             idx += (long long)nb*TPB) {
            attn[idx] = attn[idx] / g_denom[idx >> 13];  // /8192
        }
    }
}

// ---------------------------------------------------------------------------
extern "C" void kernel_launch(void* const* d_in, const int* in_sizes, int n_in,
                              void* d_out, int out_size)
{
    const float* enc    = (const float*)d_in[0];
    const float* hidden = (const float*)d_in[1];
    const float* embed  = (const float*)d_in[2];
    const float* w_ih   = (const float*)d_in[3];
    const float* w_hh   = (const float*)d_in[4];
    const float* b_ih   = (const float*)d_in[5];
    const float* b_hh   = (const float*)d_in[6];
    const float* w_out  = (const float*)d_in[7];
    const float* b_out  = (const float*)d_in[8];
    float*       out    = (float*)d_out;

    int dev = 0, sm = 0;
    cudaGetDevice(&dev);
    cudaDeviceGetAttribute(&sm, cudaDevAttrMultiProcessorCount, dev);
    int nb = sm;
    if (nb > MAXB) nb = MAXB;
    if (nb < 64)   nb = 64;      // GRU needs 512 warps resident

    cudaFuncSetAttribute(gi_kernel, cudaFuncAttributeMaxDynamicSharedMemorySize, 81920);
    cudaFuncSetAttribute(wv_kernel, cudaFuncAttributeMaxDynamicSharedMemorySize, 81920);

    init_kernel<<<1, 32>>>();
    gi_kernel<<<192, 256, 81920>>>(w_ih, b_ih, embed);
    wv_kernel<<<256, 256, 81920>>>(enc, w_out);
    dec_main<<<nb, TPB>>>(enc, hidden, w_hh, b_hh, w_out, b_out, out);
}

// round 2
// speedup vs baseline: 1.7395x; 1.7395x over previous
#include <cuda_runtime.h>
#include <math.h>

#define Vv      40
#define Ee      512
#define Hh      512
#define DKk     512
#define DVv     512
#define TENC    8192
#define MAXLEN  200
#define EOSI    38
#define SCALE   0.04419417382415922f   /* 1/sqrt(512) */

#define NB      128          /* blocks; 8192/128=64 keys, 512/128=4 rows each */
#define TPB     1024
#define ROWS_PB 4
#define KEYS_PB 64

// -------- persistent device scratch --------
__device__ float    g_GI[3*Hh*Vv];      // w_ih @ embed^T + b_ih   [1536][40]
__device__ float    g_WV[TENC*Vv];      // values @ w_out[:, :512]^T  [8192][40]
__device__ float    g_hbuf[2][Hh];      // hidden ping-pong
__device__ float    g_pU[Vv*NB];        // partials, layout [k][block]
__device__ float    g_pDen[NB];         // per-block denom partials
__device__ float    g_pOutH[Vv];        // w_out[:,512:] @ h
__device__ unsigned g_flags[NB*32];     // per-block epoch flag, 128B padded

// -------- release/acquire flag ops (no fences, no L1 flush) --------
__device__ __forceinline__ void relstore(unsigned* p, unsigned v) {
    asm volatile("st.release.gpu.u32 [%0], %1;" :: "l"(p), "r"(v) : "memory");
}
__device__ __forceinline__ unsigned acqload(unsigned* p) {
    unsigned v;
    asm volatile("ld.acquire.gpu.u32 %0, [%1];" : "=r"(v) : "l"(p) : "memory");
    return v;
}

__global__ void init_kernel()
{
    for (int i = threadIdx.x; i < NB*32; i += blockDim.x) g_flags[i] = 0u;
}

// -------- GI = w_ih @ embed^T + b_ih : one warp per row of w_ih -------------
__global__ void gi_kernel(const float* __restrict__ w_ih,
                          const float* __restrict__ b_ih,
                          const float* __restrict__ embed)
{
    extern __shared__ float sE[];              // embed [40][512] = 80 KB
    for (int i = threadIdx.x; i < Vv*Ee; i += blockDim.x) sE[i] = embed[i];
    __syncthreads();

    int lane = threadIdx.x & 31;
    int gid  = blockIdx.x * (blockDim.x >> 5) + (threadIdx.x >> 5);
    if (gid >= 3*Hh) return;

    float wreg[16];
    const float* wr = w_ih + (size_t)gid * Ee;
    #pragma unroll
    for (int j = 0; j < 16; ++j) wreg[j] = wr[lane + 32*j];
    float bb = b_ih[gid];

    for (int v = 0; v < Vv; ++v) {
        float a = 0.f;
        #pragma unroll
        for (int j = 0; j < 16; ++j) a = fmaf(wreg[j], sE[v*Ee + lane + 32*j], a);
        #pragma unroll
        for (int o = 16; o > 0; o >>= 1) a += __shfl_down_sync(0xffffffffu, a, o);
        if (lane == 0) g_GI[(size_t)gid*Vv + v] = a + bb;
    }
}

// -------- WV[t][k] = dot(values[t], w_out[k][0:512]) : one warp per t -------
__global__ void wv_kernel(const float* __restrict__ enc,
                          const float* __restrict__ w_out)
{
    extern __shared__ float sW[];              // w_out[:, :512] [40][512] = 80 KB
    for (int i = threadIdx.x; i < Vv*DVv; i += blockDim.x) {
        int k = i / DVv, j = i % DVv;
        sW[i] = w_out[(size_t)k*(DVv+Hh) + j];
    }
    __syncthreads();

    int lane  = threadIdx.x & 31;
    int gw    = blockIdx.x * (blockDim.x >> 5) + (threadIdx.x >> 5);
    int wspan = gridDim.x  * (blockDim.x >> 5);

    for (int t = gw; t < TENC; t += wspan) {
        float4 vreg[4];
        const float4* vr = (const float4*)(enc + (size_t)t*(DKk+DVv) + DKk);
        #pragma unroll
        for (int j = 0; j < 4; ++j) vreg[j] = vr[lane + 32*j];
        for (int k = 0; k < Vv; ++k) {
            const float4* wk = (const float4*)(sW + k*DVv);
            float a = 0.f;
            #pragma unroll
            for (int j = 0; j < 4; ++j) {
                float4 w = wk[lane + 32*j];
                a = fmaf(vreg[j].x, w.x, a);
                a = fmaf(vreg[j].y, w.y, a);
                a = fmaf(vreg[j].z, w.z, a);
                a = fmaf(vreg[j].w, w.w, a);
            }
            #pragma unroll
            for (int o = 16; o > 0; o >>= 1) a += __shfl_down_sync(0xffffffffu, a, o);
            if (lane == 0) g_WV[(size_t)t*Vv + k] = a;
        }
    }
}

// -------- persistent decoder kernel ----------------------------------------
__global__ void __launch_bounds__(TPB, 1)
dec_main(const float* __restrict__ enc,
         const float* __restrict__ hidden,
         const float* __restrict__ w_hh,
         const float* __restrict__ b_hh,
         const float* __restrict__ w_out,
         const float* __restrict__ b_out,
         float*       __restrict__ dout)
{
    __shared__ float h_sh[Hh];
    __shared__ float sG[ROWS_PB][8][3];
    __shared__ float sU[32][41];
    __shared__ float sDen[32];
    __shared__ float sR[Vv][13];
    __shared__ float s_invden;
    __shared__ int   s_best;

    const int tid  = threadIdx.x;
    const int wid  = tid >> 5;
    const int lane = tid & 31;
    const int b    = blockIdx.x;

    float* attn = dout + (MAXLEN*Vv + 1);

    const int t0   = b * KEYS_PB;
    const int row0 = b * ROWS_PB;
    int mylen = MAXLEN;                        // block0/thread0 only

    for (int s = 0; s <= MAXLEN; ++s) {
        // ---- wait: phase-2 of step s-1 complete on all blocks ----
        if (s > 0) {
            if (tid < NB) { while (acqload(&g_flags[tid*32]) < 2u*(unsigned)s) { } }
        }
        __syncthreads();

        // ---- phase 1a: load h_prev + parallel partial reduce ----
        if (s < MAXLEN) {
            const float* hsrc = (s == 0) ? hidden : g_hbuf[(s-1)&1];
            if (tid < Hh) h_sh[tid] = __ldcg(hsrc + tid);
        }
        if (s > 0) {
            if (tid < 480) {
                int k = tid / 12, j = tid % 12;
                float a = 0.f;
                for (int p = j; p < NB; p += 12) a += __ldcg(&g_pU[k*NB + p]);
                sR[k][j] = a;
            } else if (tid >= 992) {                     // warp 31: denom
                int j = tid - 992;
                float d = 0.f;
                #pragma unroll
                for (int p = 0; p < NB/32; ++p) d += __ldcg(&g_pDen[j + 32*p]);
                #pragma unroll
                for (int o = 16; o > 0; o >>= 1) d += __shfl_xor_sync(0xffffffffu, d, o);
                if (j == 0) s_invden = 1.0f / d;
            }
        }
        __syncthreads();

        // ---- phase 1b: logits + argmax (warp 0) ----
        if (s > 0 && wid == 0) {
            float inv = s_invden;
            float v1, v2 = -3.4e38f;
            int   k1 = lane, k2 = lane + 32;
            {
                float a = 0.f;
                #pragma unroll
                for (int j = 0; j < 12; ++j) a += sR[k1][j];
                v1 = a*inv + __ldcg(&g_pOutH[k1]) + b_out[k1];
                if (b == 0) dout[(s-1)*Vv + k1] = v1;
            }
            if (lane < Vv - 32) {
                float a = 0.f;
                #pragma unroll
                for (int j = 0; j < 12; ++j) a += sR[k2][j];
                v2 = a*inv + __ldcg(&g_pOutH[k2]) + b_out[k2];
                if (b == 0) dout[(s-1)*Vv + k2] = v2;
            }
            float bv; int bi;
            if (v2 > v1) { bv = v2; bi = k2; } else { bv = v1; bi = k1; }
            #pragma unroll
            for (int o = 16; o > 0; o >>= 1) {
                float ov = __shfl_xor_sync(0xffffffffu, bv, o);
                int   oi = __shfl_xor_sync(0xffffffffu, bi, o);
                if (ov > bv || (ov == bv && oi < bi)) { bv = ov; bi = oi; }
            }
            if (lane == 0) s_best = bi;
        }
        __syncthreads();

        // ---- phase 1c: normalize previous attn row + GRU partials ----
        if (s > 0 && tid < KEYS_PB) {
            attn[(size_t)(s-1)*TENC + t0 + tid] *= s_invden;
        }
        if (s < MAXLEN) {
            int rl  = wid >> 3;                // local row 0..3
            int ch  = wid & 7;                 // 64-elem chunk 0..7
            int row = row0 + rl;
            int j0  = ch*64 + lane*2;
            const float2* w0 = (const float2*)(w_hh + (size_t)row*Hh         + j0);
            const float2* w1 = (const float2*)(w_hh + (size_t)(Hh   + row)*Hh + j0);
            const float2* w2 = (const float2*)(w_hh + (size_t)(2*Hh + row)*Hh + j0);
            float2 hv = *(const float2*)(h_sh + j0);
            float2 x0 = *w0, x1 = *w1, x2 = *w2;
            float a0 = fmaf(x0.x, hv.x, x0.y*hv.y);
            float a1 = fmaf(x1.x, hv.x, x1.y*hv.y);
            float a2 = fmaf(x2.x, hv.x, x2.y*hv.y);
            #pragma unroll
            for (int o = 16; o > 0; o >>= 1) {
                a0 += __shfl_xor_sync(0xffffffffu, a0, o);
                a1 += __shfl_xor_sync(0xffffffffu, a1, o);
                a2 += __shfl_xor_sync(0xffffffffu, a2, o);
            }
            if (lane == 0) { sG[rl][ch][0] = a0; sG[rl][ch][1] = a1; sG[rl][ch][2] = a2; }
        }
        __syncthreads();

        if (s < MAXLEN && tid < ROWS_PB) {
            int row = row0 + tid;
            float g0 = 0.f, g1 = 0.f, g2 = 0.f;
            #pragma unroll
            for (int c = 0; c < 8; ++c) {
                g0 += sG[tid][c][0]; g1 += sG[tid][c][1]; g2 += sG[tid][c][2];
            }
            int best = (s == 0) ? EOSI : s_best;
            float gir = g_GI[(size_t)row*Vv          + best];
            float giz = g_GI[(size_t)(Hh   + row)*Vv + best];
            float gin = g_GI[(size_t)(2*Hh + row)*Vv + best];
            float ghr = g0 + b_hh[row];
            float ghz = g1 + b_hh[Hh + row];
            float ghn = g2 + b_hh[2*Hh + row];
            float rr = 1.f/(1.f + __expf(-(gir + ghr)));
            float zz = 1.f/(1.f + __expf(-(giz + ghz)));
            float x  = gin + rr*ghn;
            float e2 = __expf(2.f*x);
            float nn = (e2 - 1.f)/(e2 + 1.f);
            __stcg(&g_hbuf[s&1][row], (1.f - zz)*nn + zz*h_sh[row]);
        }
        if (s > 0 && b == 0 && tid == 0) {
            if (s_best == EOSI && mylen == MAXLEN) mylen = s - 1;
        }
        __syncthreads();

        if (s == MAXLEN) break;

        if (tid == 0) relstore(&g_flags[b*32], 2u*(unsigned)s + 1u);
        if (tid < NB) { while (acqload(&g_flags[tid*32]) < 2u*(unsigned)s + 1u) { } }
        __syncthreads();

        // ---- phase 2: attention over this block's 64 keys ----
        if (tid < Hh) h_sh[tid] = __ldcg(&g_hbuf[s&1][tid]);
        __syncthreads();

        // blocks 1..40: one row each of w_out[:,512:] @ h  (warp 31)
        if (b >= 1 && b <= Vv && wid == 31) {
            int k = b - 1;
            const float4* wr  = (const float4*)(w_out + (size_t)k*(DVv+Hh) + DVv);
            const float4* hv4 = (const float4*)h_sh;
            float acc = 0.f;
            #pragma unroll
            for (int j = 0; j < 4; ++j) {
                float4 w = wr[lane + 32*j], h = hv4[lane + 32*j];
                acc = fmaf(w.x, h.x, acc); acc = fmaf(w.y, h.y, acc);
                acc = fmaf(w.z, h.z, acc); acc = fmaf(w.w, h.w, acc);
            }
            #pragma unroll
            for (int o = 16; o > 0; o >>= 1) acc += __shfl_xor_sync(0xffffffffu, acc, o);
            if (lane == 0) __stcg(&g_pOutH[k], acc);
        }

        {
            const float4* hv4 = (const float4*)h_sh;
            float4 h0 = hv4[lane], h1 = hv4[lane+32], h2 = hv4[lane+64], h3 = hv4[lane+96];
            float acc0 = 0.f, acc1 = 0.f, den = 0.f;
            #pragma unroll
            for (int it = 0; it < 2; ++it) {
                int t = t0 + wid + it*32;
                const float4* kr = (const float4*)(enc + (size_t)t*(DKk+DVv));
                float4 k0 = kr[lane], k1 = kr[lane+32], k2 = kr[lane+64], k3 = kr[lane+96];
                float a = 0.f;
                a = fmaf(k0.x, h0.x, a); a = fmaf(k0.y, h0.y, a);
                a = fmaf(k0.z, h0.z, a); a = fmaf(k0.w, h0.w, a);
                a = fmaf(k1.x, h1.x, a); a = fmaf(k1.y, h1.y, a);
                a = fmaf(k1.z, h1.z, a); a = fmaf(k1.w, h1.w, a);
                a = fmaf(k2.x, h2.x, a); a = fmaf(k2.y, h2.y, a);
                a = fmaf(k2.z, h2.z, a); a = fmaf(k2.w, h2.w, a);
                a = fmaf(k3.x, h3.x, a); a = fmaf(k3.y, h3.y, a);
                a = fmaf(k3.z, h3.z, a); a = fmaf(k3.w, h3.w, a);
                #pragma unroll
                for (int o = 16; o > 0; o >>= 1) a += __shfl_xor_sync(0xffffffffu, a, o);
                float e = __expf(a * SCALE);
                if (lane == 0) attn[(size_t)s*TENC + t] = e;     // unnormalized
                den += e;
                acc0 = fmaf(e, g_WV[(size_t)t*Vv + lane], acc0);
                if (lane < Vv - 32)
                    acc1 = fmaf(e, g_WV[(size_t)t*Vv + 32 + lane], acc1);
            }
            sU[wid][lane] = acc0;
            if (lane < Vv - 32) sU[wid][32 + lane] = acc1;
            if (lane == 0) sDen[wid] = den;
        }
        __syncthreads();

        if (tid < Vv) {
            float a = 0.f;
            #pragma unroll
            for (int w = 0; w < 32; ++w) a += sU[w][tid];
            __stcg(&g_pU[tid*NB + b], a);
        } else if (tid == Vv) {
            float d = 0.f;
            #pragma unroll
            for (int w = 0; w < 32; ++w) d += sDen[w];
            __stcg(&g_pDen[b], d);
        }
        __syncthreads();
        if (tid == 0) relstore(&g_flags[b*32], 2u*(unsigned)s + 2u);
    }

    if (b == 0 && tid == 0) dout[MAXLEN*Vv] = (float)mylen;   // lens
}

// ---------------------------------------------------------------------------
extern "C" void kernel_launch(void* const* d_in, const int* in_sizes, int n_in,
                              void* d_out, int out_size)
{
    const float* enc    = (const float*)d_in[0];
    const float* hidden = (const float*)d_in[1];
    const float* embed  = (const float*)d_in[2];
    const float* w_ih   = (const float*)d_in[3];
    const float* w_hh   = (const float*)d_in[4];
    const float* b_ih   = (const float*)d_in[5];
    const float* b_hh   = (const float*)d_in[6];
    const float* w_out  = (const float*)d_in[7];
    const float* b_out  = (const float*)d_in[8];
    float*       out    = (float*)d_out;

    cudaFuncSetAttribute(gi_kernel, cudaFuncAttributeMaxDynamicSharedMemorySize, 81920);
    cudaFuncSetAttribute(wv_kernel, cudaFuncAttributeMaxDynamicSharedMemorySize, 81920);

    init_kernel<<<1, 256>>>();
    gi_kernel<<<192, 256, 81920>>>(w_ih, b_ih, embed);
    wv_kernel<<<256, 256, 81920>>>(enc, w_out);
    dec_main<<<NB, TPB>>>(enc, hidden, w_hh, b_hh, w_out, b_out, out);
}